// round 14
// baseline (speedup 1.0000x reference)
#include <cuda_runtime.h>
#include <cstdint>
#include <cstddef>

#define T_STEPS    64
#define INPUT_BITS 1024
#define N_STATE    2048
#define N_OUT      256
#define HASH       65536

#define NCTAS    8
#define THREADS  256                     // 8 * 256 = 2048 -> one thread per neuron
#define WPC      (THREADS / 32)          // 8 warps -> 8 state words per CTA

// All bit words live in 8-byte slots: lo = packed bits, hi = sequence tag.
// Slot index space (per CTA):
//   [0, 2048)      : window slots; step t -> slots [t*32, t*32+32), hi = t-1
//   [2048, 2112)   : state buffer 0 (read at even t), hi = seq of producing step
//   [2112, 2176)   : state buffer 1 (read at odd t)
#define STATE_BASE  2048
#define NSLOTS      2176

// -------- helpers ------------------------------------------------------------
__device__ __forceinline__ uint32_t smem_u32(const void* p) {
    uint32_t a;
    asm("{ .reg .u64 t; cvta.to.shared.u64 t, %1; cvt.u32.u64 %0, t; }"
        : "=r"(a) : "l"(p));
    return a;
}
__device__ __forceinline__ uint32_t cluster_rank() {
    uint32_t r;
    asm("mov.u32 %0, %%cluster_ctarank;" : "=r"(r));
    return r;
}
__device__ __forceinline__ uint32_t mapa_u32(uint32_t laddr, uint32_t rank) {
    uint32_t raddr;
    asm("mapa.shared::cluster.u32 %0, %1, %2;" : "=r"(raddr) : "r"(laddr), "r"(rank));
    return raddr;
}
// 8B relaxed store into a (possibly remote) cluster CTA's smem.
__device__ __forceinline__ void st_slot(uint32_t raddr, unsigned long long v) {
    asm volatile("st.relaxed.cluster.shared::cluster.b64 [%0], %1;"
                 :: "r"(raddr), "l"(v) : "memory");
}
// 8B relaxed load from local smem (cluster scope: written by peer CTAs).
__device__ __forceinline__ unsigned long long ld_slot(uint32_t laddr) {
    unsigned long long v;
    asm volatile("ld.relaxed.cluster.shared::cta.b64 %0, [%1];"
                 : "=l"(v) : "r"(laddr) : "memory");
    return v;
}
#define CLUSTER_SYNC() do {                                              \
    asm volatile("barrier.cluster.arrive.aligned;" ::: "memory");        \
    asm volatile("barrier.cluster.wait.aligned;"   ::: "memory");        \
} while (0)

// ---------------------------------------------------------------------------
// Dataflow recurrence: no mbarriers, no cluster barrier in the loop.
// Producers push (word, seq=t) slots; consumers spin until seq == t-1.
__global__ __launch_bounds__(THREADS)
__cluster_dims__(NCTAS, 1, 1)
void recurrent_kernel(
    const int*   __restrict__ input_bits,
    const int*   __restrict__ conn_state,
    const float* __restrict__ state_table,
    const int*   __restrict__ conn_out,
    const float* __restrict__ output_table,
    float*       __restrict__ out)
{
    __shared__ __align__(16) unsigned long long slots[NSLOTS];

    const int tid  = threadIdx.x;
    const int lane = tid & 31;
    const int warp = tid >> 5;                       // 0..7
    const uint32_t rank = cluster_rank();
    const int n  = (int)rank * THREADS + tid;        // my state neuron
    const int g  = (int)rank * WPC + warp;           // my warp's state word 0..63

    const uint32_t sb = smem_u32(slots);

    // ---- startup: pack all 64 windows into (bits, t-1) slots -----------------
#pragma unroll
    for (int k = 0; k < 2048 / THREADS; k++) {
        const int W = k * THREADS + tid;             // 0..2047 ; t = W>>5
        const int4* p = reinterpret_cast<const int4*>(input_bits) + W * 8;
        unsigned bword = 0;
#pragma unroll
        for (int q = 0; q < 8; q++) {
            const int4 v = p[q];
            bword |= ((unsigned)v.x << (q * 4 + 0))
                   | ((unsigned)v.y << (q * 4 + 1))
                   | ((unsigned)v.z << (q * 4 + 2))
                   | ((unsigned)v.w << (q * 4 + 3));
        }
        const unsigned seq = (unsigned)((W >> 5) - 1);          // t-1 (t=0 -> ~0u)
        slots[W] = (unsigned long long)bword | ((unsigned long long)seq << 32);
    }
    // state slots: data 0, seq = ~0u  (matches want at t=0 -> zero initial state)
    if (tid < 128)
        slots[STATE_BASE + tid] = 0xFFFFFFFF00000000ull;

    // ---- preload my 16 connections, encoded as (slot_base<<5 | shift) -------
    int enc[16];
    {
        const int4* c4 = reinterpret_cast<const int4*>(conn_state) + n * 4;
        int4 a0 = c4[0], a1 = c4[1], a2 = c4[2], a3 = c4[3];
        int raw[16] = { a0.x,a0.y,a0.z,a0.w, a1.x,a1.y,a1.z,a1.w,
                        a2.x,a2.y,a2.z,a2.w, a3.x,a3.y,a3.z,a3.w };
#pragma unroll
        for (int j = 0; j < 16; j++) {
            const int ci = raw[j];
            const int sh = ci & 31;
            const int base = (ci < INPUT_BITS) ? (ci >> 5)
                                               : (STATE_BASE + ((ci - INPUT_BITS) >> 5));
            enc[j] = (base << 5) | sh;
        }
    }
    const float* trow = state_table + (size_t)n * HASH;

    // ---- precompute push targets for both parities (lanes 0..NCTAS-1) -------
    // push after step t -> state buffer (t+1)&1, slot word g, in every CTA.
    uint32_t rd0 = 0, rd1 = 0;
    if (lane < NCTAS) {
        rd0 = mapa_u32(sb + (uint32_t)(STATE_BASE      + g) * 8u, (uint32_t)lane);
        rd1 = mapa_u32(sb + (uint32_t)(STATE_BASE + 64 + g) * 8u, (uint32_t)lane);
    }

    __syncthreads();        // local slot init complete
    CLUSTER_SYNC();         // every CTA initialized before any push can land

    // ---- recurrence: uniform loop, no peel, no barrier -----------------------
    for (int t = 0; t < T_STEPS; t++) {
        const unsigned want = (unsigned)(t - 1);     // seq to wait for
        const int woff = t << 5;                     // window slot offset
        const int boff = (t & 1) << 6;               // state buffer offset

        unsigned acc = 0;
#pragma unroll
        for (int j = 0; j < 16; j++) {
            const int e    = enc[j];
            const int base = e >> 5;
            const int idx  = base + ((base < STATE_BASE) ? woff : boff);
            const uint32_t a = sb + (uint32_t)idx * 8u;
            unsigned long long v = ld_slot(a);
            while ((unsigned)(v >> 32) != want)      // spin until producer's push lands
                v = ld_slot(a);
            acc |= (((unsigned)v >> (e & 31)) & 1u) << j;
        }

        const float fv = __ldg(trow + acc);
        const unsigned bal = __ballot_sync(0xffffffffu, fv > 0.5f);

        // push (word, seq=t) into ALL cluster CTAs' next-parity state buffer
        if (lane < NCTAS) {
            const unsigned long long sv =
                (unsigned long long)bal | ((unsigned long long)(unsigned)t << 32);
            st_slot(((t + 1) & 1) ? rd1 : rd0, sv);
        }
    }

    // ---- final: releases all pushes / keeps smem alive for in-flight stores --
    CLUSTER_SYNC();

    if (rank == 0) {
        // final state (seq 63) lives in buffer 0: slots [STATE_BASE, +64)
        for (int o = tid; o < N_OUT; o += THREADS) {
            const int4* c4 = reinterpret_cast<const int4*>(conn_out) + o * 4;
            int4 a0 = c4[0], a1 = c4[1], a2 = c4[2], a3 = c4[3];
            int co[16] = { a0.x,a0.y,a0.z,a0.w, a1.x,a1.y,a1.z,a1.w,
                           a2.x,a2.y,a2.z,a2.w, a3.x,a3.y,a3.z,a3.w };
            unsigned addr = 0;
#pragma unroll
            for (int j = 0; j < 16; j++) {
                const int ci = co[j];
                addr |= (((unsigned)slots[STATE_BASE + (ci >> 5)] >> (ci & 31)) & 1u) << j;
            }
            out[o] = __ldg(output_table + (size_t)o * HASH + addr);
        }
    }
}

// ---------------------------------------------------------------------------
extern "C" void kernel_launch(void* const* d_in, const int* in_sizes, int n_in,
                              void* d_out, int out_size)
{
    const int*   input_bits   = (const int*)  d_in[0];  // [65536]
    const int*   conn_state   = (const int*)  d_in[1];  // [2048*16]
    const int*   conn_out     = (const int*)  d_in[2];  // [256*16]
    const float* state_table  = (const float*)d_in[3];  // [2048*65536]
    const float* output_table = (const float*)d_in[4];  // [256*65536]
    float*       out          = (float*)d_out;          // [256]

    recurrent_kernel<<<NCTAS, THREADS>>>(
        input_bits, conn_state, state_table, conn_out, output_table, out);
}

// round 17
// speedup vs baseline: 1.2282x; 1.2282x over previous
#include <cuda_runtime.h>
#include <cstdint>
#include <cstddef>

#define T_STEPS    64
#define INPUT_BITS 1024
#define N_STATE    2048
#define N_OUT      256
#define HASH       65536

#define NCTAS    8
#define THREADS  256                     // 8 * 256 = 2048 -> one thread per neuron
#define WPC      (THREADS / 32)          // 8 warps -> 8 state words per CTA

// All bit words live in 8-byte slots: lo = packed bits, hi = sequence tag.
// Slot index space (per CTA):
//   [0, 2048)      : window slots; step t -> slots [t*32, t*32+32), tag = t-1
//   [2048, 2304)   : state slots, 4 buffers x 64 words; buffer b read at t%4==b,
//                    written by step t-1 pushes with tag t-1
#define STATE_BASE  2048
#define NSLOTS      2304                 // 2048 + 4*64

// -------- helpers ------------------------------------------------------------
__device__ __forceinline__ uint32_t smem_u32(const void* p) {
    uint32_t a;
    asm("{ .reg .u64 t; cvta.to.shared.u64 t, %1; cvt.u32.u64 %0, t; }"
        : "=r"(a) : "l"(p));
    return a;
}
__device__ __forceinline__ uint32_t cluster_rank() {
    uint32_t r;
    asm("mov.u32 %0, %%cluster_ctarank;" : "=r"(r));
    return r;
}
__device__ __forceinline__ uint32_t mapa_u32(uint32_t laddr, uint32_t rank) {
    uint32_t raddr;
    asm("mapa.shared::cluster.u32 %0, %1, %2;" : "=r"(raddr) : "r"(laddr), "r"(rank));
    return raddr;
}
// 8B relaxed store into a (possibly remote) cluster CTA's smem.
__device__ __forceinline__ void st_slot(uint32_t raddr, unsigned long long v) {
    asm volatile("st.relaxed.cluster.shared::cluster.b64 [%0], %1;"
                 :: "r"(raddr), "l"(v) : "memory");
}
// 8B relaxed load from local smem (written by peer CTAs). volatile => reloads
// every poll; no memory clobber so the 16 loads of one poll batch freely.
__device__ __forceinline__ unsigned long long ld_slot(uint32_t laddr) {
    unsigned long long v;
    asm volatile("ld.relaxed.cluster.shared::cta.b64 %0, [%1];"
                 : "=l"(v) : "r"(laddr));
    return v;
}
#define CLUSTER_SYNC() do {                                              \
    asm volatile("barrier.cluster.arrive.aligned;" ::: "memory");        \
    asm volatile("barrier.cluster.wait.aligned;"   ::: "memory");        \
} while (0)

// ---------------------------------------------------------------------------
// Dataflow recurrence with batched polling: per step, each thread loads all 16
// of its slots (full MLP), ORs the tag mismatches, and retries the whole batch
// until every slot carries tag t-1. No mbarriers, no barriers in the loop.
__global__ __launch_bounds__(THREADS)
__cluster_dims__(NCTAS, 1, 1)
void recurrent_kernel(
    const int*   __restrict__ input_bits,
    const int*   __restrict__ conn_state,
    const float* __restrict__ state_table,
    const int*   __restrict__ conn_out,
    const float* __restrict__ output_table,
    float*       __restrict__ out)
{
    __shared__ __align__(16) unsigned long long slots[NSLOTS];

    const int tid  = threadIdx.x;
    const int lane = tid & 31;
    const int warp = tid >> 5;                       // 0..7
    const uint32_t rank = cluster_rank();
    const int n  = (int)rank * THREADS + tid;        // my state neuron
    const int g  = (int)rank * WPC + warp;           // my warp's state word 0..63

    const uint32_t sb = smem_u32(slots);

    // ---- startup: pack all 64 windows into (bits, t-1) slots -----------------
#pragma unroll
    for (int k = 0; k < 2048 / THREADS; k++) {
        const int W = k * THREADS + tid;             // 0..2047 ; t = W>>5
        const int4* p = reinterpret_cast<const int4*>(input_bits) + W * 8;
        unsigned bword = 0;
#pragma unroll
        for (int q = 0; q < 8; q++) {
            const int4 v = p[q];
            bword |= ((unsigned)v.x << (q * 4 + 0))
                   | ((unsigned)v.y << (q * 4 + 1))
                   | ((unsigned)v.z << (q * 4 + 2))
                   | ((unsigned)v.w << (q * 4 + 3));
        }
        const unsigned seq = (unsigned)((W >> 5) - 1);          // t-1 (t=0 -> ~0u)
        slots[W] = (unsigned long long)bword | ((unsigned long long)seq << 32);
    }
    // state slots: buffer 0 = (data 0, tag ~0u) -> matches want at t=0 (zero
    // initial state); buffers 1..3 get a tag that matches no step.
    {
        const unsigned long long init0 = 0xFFFFFFFF00000000ull;
        const unsigned long long initX = 0xFFFFFFFE00000000ull;
        slots[STATE_BASE + tid] = (tid < 64) ? init0 : initX;   // 256 slots, 256 thr
    }

    // ---- preload my 16 connections, encoded as (slot_base<<5 | shift) -------
    int enc[16];
    {
        const int4* c4 = reinterpret_cast<const int4*>(conn_state) + n * 4;
        int4 a0 = c4[0], a1 = c4[1], a2 = c4[2], a3 = c4[3];
        int raw[16] = { a0.x,a0.y,a0.z,a0.w, a1.x,a1.y,a1.z,a1.w,
                        a2.x,a2.y,a2.z,a2.w, a3.x,a3.y,a3.z,a3.w };
#pragma unroll
        for (int j = 0; j < 16; j++) {
            const int ci = raw[j];
            const int sh = ci & 31;
            const int base = (ci < INPUT_BITS) ? (ci >> 5)
                                               : (STATE_BASE + ((ci - INPUT_BITS) >> 5));
            enc[j] = (base << 5) | sh;
        }
    }
    const float* trow = state_table + (size_t)n * HASH;

    // ---- precompute push targets for all 4 buffer parities (lanes 0..7) -----
    uint32_t rd0 = 0, rd1 = 0, rd2 = 0, rd3 = 0;
    if (lane < NCTAS) {
        rd0 = mapa_u32(sb + (uint32_t)(STATE_BASE +   0 + g) * 8u, (uint32_t)lane);
        rd1 = mapa_u32(sb + (uint32_t)(STATE_BASE +  64 + g) * 8u, (uint32_t)lane);
        rd2 = mapa_u32(sb + (uint32_t)(STATE_BASE + 128 + g) * 8u, (uint32_t)lane);
        rd3 = mapa_u32(sb + (uint32_t)(STATE_BASE + 192 + g) * 8u, (uint32_t)lane);
    }

    __syncthreads();        // local slot init complete
    CLUSTER_SYNC();         // every CTA initialized before any push can land

    // ---- recurrence: uniform loop, batched poll, no barriers -----------------
    for (int t = 0; t < T_STEPS; t++) {
        const unsigned want = (unsigned)(t - 1);     // tag to wait for (uniform)
        const int woff = t << 5;                     // window slot offset
        const int boff = (t & 3) << 6;               // state buffer offset (4-deep)

        unsigned acc, bad;
        do {
            acc = 0; bad = 0;
#pragma unroll
            for (int j = 0; j < 16; j++) {
                const int e    = enc[j];
                const int base = e >> 5;
                const int idx  = base + ((base < STATE_BASE) ? woff : boff);
                const unsigned long long v = ld_slot(sb + (uint32_t)idx * 8u);
                bad |= ((unsigned)(v >> 32)) ^ want;
                acc |= (((unsigned)v >> (e & 31)) & 1u) << j;
            }
        } while (bad != 0);

        const float fv = __ldg(trow + acc);
        const unsigned bal = __ballot_sync(0xffffffffu, fv > 0.5f);

        // push (word, tag=t) into ALL cluster CTAs' buffer (t+1)%4
        if (lane < NCTAS) {
            const unsigned p = (unsigned)((t + 1) & 3);
            const uint32_t rdsel = (p & 2u) ? ((p & 1u) ? rd3 : rd2)
                                            : ((p & 1u) ? rd1 : rd0);
            const unsigned long long sv =
                (unsigned long long)bal | ((unsigned long long)(unsigned)t << 32);
            st_slot(rdsel, sv);
        }
    }

    // ---- final: releases all pushes / keeps smem alive for in-flight stores --
    CLUSTER_SYNC();

    if (rank == 0) {
        // final state (tag 63) lives in buffer (63+1)%4 = 0: slots [STATE_BASE, +64)
        for (int o = tid; o < N_OUT; o += THREADS) {
            const int4* c4 = reinterpret_cast<const int4*>(conn_out) + o * 4;
            int4 a0 = c4[0], a1 = c4[1], a2 = c4[2], a3 = c4[3];
            int co[16] = { a0.x,a0.y,a0.z,a0.w, a1.x,a1.y,a1.z,a1.w,
                           a2.x,a2.y,a2.z,a2.w, a3.x,a3.y,a3.z,a3.w };
            unsigned addr = 0;
#pragma unroll
            for (int j = 0; j < 16; j++) {
                const int ci = co[j];
                addr |= (((unsigned)slots[STATE_BASE + (ci >> 5)] >> (ci & 31)) & 1u) << j;
            }
            out[o] = __ldg(output_table + (size_t)o * HASH + addr);
        }
    }
}

// ---------------------------------------------------------------------------
extern "C" void kernel_launch(void* const* d_in, const int* in_sizes, int n_in,
                              void* d_out, int out_size)
{
    const int*   input_bits   = (const int*)  d_in[0];  // [65536]
    const int*   conn_state   = (const int*)  d_in[1];  // [2048*16]
    const int*   conn_out     = (const int*)  d_in[2];  // [256*16]
    const float* state_table  = (const float*)d_in[3];  // [2048*65536]
    const float* output_table = (const float*)d_in[4];  // [256*65536]
    float*       out          = (float*)d_out;          // [256]

    recurrent_kernel<<<NCTAS, THREADS>>>(
        input_bits, conn_state, state_table, conn_out, output_table, out);
}